// round 16
// baseline (speedup 1.0000x reference)
#include <cuda_runtime.h>
#include <cstdint>
#include <math.h>

#define BB   128      // batch
#define TT   256      // timesteps
#define HH   512      // hidden
#define EE   300      // embed dim
#define GG   2048     // 4H
#define HB   (HH*BB)

// ---------------- device scratch (static, no allocation) ----------------
__device__ float g_xproj[(size_t)TT * GG * BB];      // [t][col][b]  256MB
__device__ float g_Wq0[(size_t)128 * 512 * 16];      // [c][k][l]  4MB
__device__ float g_Wq1[(size_t)128 * 1024 * 16];     // [c][k][l]  8MB
__device__ float g_h0t[2 * HB];                      // transposed [k][b], ping-pong
__device__ float g_h1t[2 * HB];
__device__ unsigned g_flagH0[16 * 32];               // per-chunk monotonic flags
__device__ unsigned g_flagH1[16 * 32];               // (128B stride)
__device__ int g_odd_nonzero;

// ---------------- helpers ----------------
typedef unsigned long long ull;

__device__ __forceinline__ ull bcast2(float v) {
    ull r; asm("mov.b64 %0, {%1, %1};" : "=l"(r) : "f"(v)); return r;
}
__device__ __forceinline__ ull fma2(ull a, ull b, ull c) {
    ull d; asm("fma.rn.f32x2 %0, %1, %2, %3;" : "=l"(d) : "l"(a), "l"(b), "l"(c)); return d;
}
__device__ __forceinline__ ull add2(ull a, ull b) {
    ull d; asm("add.rn.f32x2 %0, %1, %2;" : "=l"(d) : "l"(a), "l"(b)); return d;
}
__device__ __forceinline__ float2 unpk2(ull v) {
    float2 f; asm("mov.b64 {%0, %1}, %2;" : "=f"(f.x), "=f"(f.y) : "l"(v)); return f;
}
// fast gate nonlinearities (MUFU-based). Inf-safe: __fdividef(1, inf) -> 0.
__device__ __forceinline__ float sigf(float x) {
    return __fdividef(1.0f, 1.0f + __expf(-x));
}
__device__ __forceinline__ float tanhf_fast(float x) {
    x = fminf(fmaxf(x, -15.0f), 15.0f);
    float e = __expf(2.0f * x);
    return __fdividef(e - 1.0f, e + 1.0f);
}

// per-chunk flag ops (monotonic, release/acquire, no reset)
__device__ __forceinline__ void arrive_flag(unsigned* f) {
    asm volatile("red.release.gpu.global.add.u32 [%0], 1;" :: "l"(f) : "memory");
}
__device__ __forceinline__ void poll_flag(const unsigned* f, unsigned target) {
    unsigned v;
    do {
        asm volatile("ld.acquire.gpu.global.u32 %0, [%1];"
                     : "=r"(v) : "l"(f) : "memory");
    } while (v < target);
}

__device__ __forceinline__ void cp16(uint32_t saddr, const float* g) {
    asm volatile("cp.async.cg.shared.global [%0], [%1], 16;" :: "r"(saddr), "l"(g));
}
__device__ __forceinline__ void cp_commit() { asm volatile("cp.async.commit_group;"); }
__device__ __forceinline__ void cp_wait1()  { asm volatile("cp.async.wait_group 1;"); }
__device__ __forceinline__ void cp_wait0()  { asm volatile("cp.async.wait_group 0;"); }

// ---------------- kernel D: detect int32 vs int64 layout of x ----------------
__global__ void detect_kernel(const int* __restrict__ xw, int nwords) {
    int i = blockIdx.x * blockDim.x + threadIdx.x;
    int odd = 2 * i + 1;
    if (odd < nwords && xw[odd] != 0) atomicOr(&g_odd_nonzero, 1);
}

// ---------------- kernel P: pack weights [c][k][l] + zero state/flags ----------------
// l -> gcol = (l>>2)*512 + c*4 + (l&3)   (gate = l>>2, hcol = l&3)
__global__ void pack_kernel(const float* __restrict__ W0,
                            const float* __restrict__ W1) {
    size_t i = (size_t)blockIdx.x * blockDim.x + threadIdx.x;
    const size_t N0 = (size_t)128 * 512 * 16;    // 1,048,576
    const size_t N1 = (size_t)128 * 1024 * 16;   // 2,097,152
    if (i < N0) {
        int c = (int)(i >> 13);
        int r = (int)(i & 8191);
        int k = r >> 4, l = r & 15;
        int gcol = ((l >> 2) << 9) + (c << 2) + (l & 3);
        g_Wq0[i] = W0[(size_t)(EE + k) * GG + gcol];
    }
    if (i < N1) {
        int c = (int)(i >> 14);
        int r = (int)(i & 16383);
        int k = r >> 4, l = r & 15;
        int gcol = ((l >> 2) << 9) + (c << 2) + (l & 3);
        g_Wq1[i] = W1[(size_t)k * GG + gcol];
    }
    if (i < 2 * HB) { g_h0t[i] = 0.0f; g_h1t[i] = 0.0f; }
    if (i < 16 * 32) { g_flagH0[i] = 0; g_flagH1[i] = 0; }
    if (i == 0) { g_odd_nonzero = 0; }
}

// ---------------- kernel A: xproj[t][col][b] ----------------
__global__ void __launch_bounds__(256) xproj_kernel(const int* __restrict__ xw,
                                                    const float* __restrict__ emb,
                                                    const float* __restrict__ W0,
                                                    const float* __restrict__ bias0,
                                                    int vmax) {
    __shared__ float s_emb[88 * 128];
    __shared__ int s_row[BB];
    const int t = blockIdx.y;
    const int colbase = blockIdx.x * 128;
    const int tid = threadIdx.x;

    const int stride = g_odd_nonzero ? 1 : 2;
    if (tid < BB) {
        int idx = xw[((size_t)tid * TT + t) * stride];
        idx = idx < 0 ? 0 : (idx > vmax ? vmax : idx);
        s_row[tid] = idx;
    }

    const int cp8 = tid & 15;
    const int bg  = tid >> 4;
    const int cb  = colbase + cp8 * 8;
    const int bi  = bg * 8;

    ull acc[8][4];
#pragma unroll
    for (int c8 = 0; c8 < 8; c8++) {
        ull bv = bcast2(bias0[cb + c8]);
#pragma unroll
        for (int p = 0; p < 4; p++) acc[c8][p] = bv;
    }
    __syncthreads();

    for (int e0 = 0; e0 < EE; e0 += 88) {
        const int ec = (EE - e0 < 88) ? (EE - e0) : 88;
        const int f4cnt = ec >> 2;
        for (int fi = tid; fi < 128 * f4cnt; fi += 256) {
            int b = fi / f4cnt, j = fi % f4cnt;
            const float4 v = *(const float4*)&emb[(size_t)s_row[b] * EE + e0 + j * 4];
            s_emb[(j * 4 + 0) * 128 + b] = v.x;
            s_emb[(j * 4 + 1) * 128 + b] = v.y;
            s_emb[(j * 4 + 2) * 128 + b] = v.z;
            s_emb[(j * 4 + 3) * 128 + b] = v.w;
        }
        __syncthreads();

#pragma unroll 4
        for (int e = 0; e < ec; e++) {
            const float* wrow = W0 + (size_t)(e0 + e) * GG + cb;
            const float4 w0v = *(const float4*)wrow;
            const float4 w1v = *(const float4*)(wrow + 4);
            float wv[8] = {w0v.x, w0v.y, w0v.z, w0v.w, w1v.x, w1v.y, w1v.z, w1v.w};
            const ulonglong2 hA = *(const ulonglong2*)&s_emb[e * 128 + bi];
            const ulonglong2 hB = *(const ulonglong2*)&s_emb[e * 128 + bi + 4];
            ull hp[4] = {hA.x, hA.y, hB.x, hB.y};
#pragma unroll
            for (int c8 = 0; c8 < 8; c8++) {
                ull w2 = bcast2(wv[c8]);
#pragma unroll
                for (int p = 0; p < 4; p++) acc[c8][p] = fma2(hp[p], w2, acc[c8][p]);
            }
        }
        __syncthreads();
    }

#pragma unroll
    for (int c8 = 0; c8 < 8; c8++) {
        size_t base = ((size_t)t * GG + cb + c8) * BB + bi;
#pragma unroll
        for (int p = 0; p < 4; p++)
            *(ull*)&g_xproj[base + p * 2] = acc[c8][p];
    }
}

// ---------------- kernel B: persistent recurrent loop (v8) ----------------
// Mainloop as v5-v7. v8: NO grid barrier — per-chunk monotonic flags.
// Each h chunk (32 k-rows) has 8 producer CTAs (CTA c -> chunk c>>3); step-t
// consumers poll flagH0[chunk] >= 8(t+1), flagH1[chunk] >= 8t one iteration
// ahead of the cp.async fill, so producer spread pipelines into the mainloop.
__global__ void __launch_bounds__(512, 1) lstm_kernel(const float* __restrict__ bias1,
                                                      const float* __restrict__ Wd,
                                                      const float* __restrict__ bd,
                                                      float* __restrict__ out) {
    extern __shared__ float smem[];
    float* s_w0    = smem;                 // [512][16]  = 8192 f
    float* s_w1    = smem + 8192;          // [1024][16] = 16384 f
    float* s_stage = smem + 24576;         // 8 slots x 4096 f (quarter q: 2q, 2q+1)
    float* gL1buf  = s_stage + 1 * 4096;   // gate staging (odd slots: dead at tail)
    float* gL0buf  = s_stage + 3 * 4096;

    const int c   = blockIdx.x;
    const int tid = threadIdx.x;
    const int q   = tid >> 7;     // quarter 0..3
    const int tl  = tid & 127;
    const int cp  = tl & 3;       // 4 cols: l = 4cp..4cp+3
    const int bg  = tl >> 2;      // 0..31
    const int b0  = bg * 4;
    const int mychunk = c >> 3;   // the h chunk this CTA produces rows into

    // gate-thread identity: gidx handles outputs (hc0, bq) and (hc0+2, bq)
    const int gidx = tid & 255;
    const int hc0  = gidx >> 7;       // 0 or 1
    const int bq   = gidx & 127;

    // ---- one-time: weights to SMEM ----
    {
        const float* w0g = g_Wq0 + (size_t)c * 8192;
        const float* w1g = g_Wq1 + (size_t)c * 16384;
        const uint32_t sw0 = (uint32_t)__cvta_generic_to_shared(s_w0);
        const uint32_t sw1 = (uint32_t)__cvta_generic_to_shared(s_w1);
        for (int i = tid; i < 2048; i += 512) cp16(sw0 + i * 16, w0g + i * 4);
        for (int i = tid; i < 4096; i += 512) cp16(sw1 + i * 16, w1g + i * 4);
        cp_commit(); cp_wait0(); __syncthreads();
    }

    float c1s[2] = {0, 0};   // tid < 256 : L1 cell state
    float c0s[2] = {0, 0};   // tid >= 256: L0 cell state

    // hoisted L1 bias addends (tid < 256 only meaningful)
    float b1r[2][4];
    if (tid < 256) {
#pragma unroll
        for (int r = 0; r < 2; r++) {
            int gc = c * 4 + hc0 + 2 * r;
#pragma unroll
            for (int g = 0; g < 4; g++) b1r[r][g] = bias1[g * 512 + gc];
        }
    }

    // ---- prologue: L0-gate threads compute h0(0) from xproj(0), c_prev = 0 ----
    if (tid >= 256) {
#pragma unroll
        for (int r = 0; r < 2; r++) {
            int hc = hc0 + 2 * r;
            int gc = c * 4 + hc;
            float gi = __ldcg(&g_xproj[((size_t)0 * GG + 0 * 512 + gc) * BB + bq]);
            float gj = __ldcg(&g_xproj[((size_t)0 * GG + 1 * 512 + gc) * BB + bq]);
            float go = __ldcg(&g_xproj[((size_t)0 * GG + 3 * 512 + gc) * BB + bq]);
            float cn = sigf(gi) * tanhf_fast(gj);
            c0s[r] = cn;
            __stcg(&g_h0t[0 * HB + gc * 128 + bq], tanhf_fast(cn) * sigf(go));
        }
    }
    __syncthreads();
    if (tid == 256) arrive_flag(&g_flagH0[mychunk * 32]);

    const uint32_t slotu[2] = {
        (uint32_t)__cvta_generic_to_shared(s_stage + (2 * q) * 4096),
        (uint32_t)__cvta_generic_to_shared(s_stage + (2 * q + 1) * 4096) };
    const float* slotf[2] = { s_stage + (2 * q) * 4096, s_stage + (2 * q + 1) * 4096 };

    for (int t = 0; t < TT; t++) {
        const float* h0src = g_h0t + (t & 1) * HB;          // h0(t)
        const float* h1src = g_h1t + ((t + 1) & 1) * HB;    // h1(t-1)
        const unsigned tgtH0 = 8u * (unsigned)(t + 1);
        const unsigned tgtH1 = 8u * (unsigned)t;

        // acc[ly*8 + pp*4 + bi]: ly0=L0, ly1=L1; pp: col pair (4cp+2pp, +1)
        ull acc[16];
#pragma unroll
        for (int i = 0; i < 16; i++) acc[i] = 0ull;

        // poll flags for the first two chunks (prime + iter0 fill)
        if (tl == 0) {
            poll_flag(&g_flagH0[q * 32], tgtH0);
            poll_flag(&g_flagH0[(q + 4) * 32], tgtH0);
        }
        asm volatile("bar.sync %0, 128;" :: "r"(1 + q) : "memory");

        // prime chunk i=0 (h0 chunk q)
        {
            const float* g = h0src + q * 4096;
#pragma unroll
            for (int p = 0; p < 8; p++) cp16(slotu[0] + (p * 128 + tl) * 16, g + (p * 128 + tl) * 4);
            cp_commit();
        }

        for (int i = 0; i < 8; i++) {
            if (i < 7) {
                const int ni = i + 1;
                const float* src = (ni < 4) ? (h0src + (q + 4 * ni) * 4096)
                                            : (h1src + (q + 4 * (ni - 4)) * 4096);
                const uint32_t sa = slotu[ni & 1];
#pragma unroll
                for (int p = 0; p < 8; p++) cp16(sa + (p * 128 + tl) * 16, src + (p * 128 + tl) * 4);
                cp_commit();
                cp_wait1();
            } else {
                cp_wait0();
            }
            asm volatile("bar.sync %0, 128;" :: "r"(1 + q) : "memory");
            const float* sh = slotf[i & 1];

            if (i < 4) {   // heavy: h0 chunk feeds both layers
                const int k0 = (q + 4 * i) * 32;
                const float* w0p = s_w0 + k0 * 16 + cp * 4;
                const float* w1p = s_w1 + k0 * 16 + cp * 4;
#pragma unroll 4
                for (int k = 0; k < 32; k++) {
                    const float4 h4 = *(const float4*)&sh[k * 128 + b0];
                    const ull hb[4] = {bcast2(h4.x), bcast2(h4.y), bcast2(h4.z), bcast2(h4.w)};
                    const ulonglong2 w0 = *(const ulonglong2*)(w0p + k * 16);
                    const ulonglong2 w1 = *(const ulonglong2*)(w1p + k * 16);
#pragma unroll
                    for (int bi = 0; bi < 4; bi++) {
                        acc[0 + bi]  = fma2(w0.x, hb[bi], acc[0 + bi]);
                        acc[4 + bi]  = fma2(w0.y, hb[bi], acc[4 + bi]);
                        acc[8 + bi]  = fma2(w1.x, hb[bi], acc[8 + bi]);
                        acc[12 + bi] = fma2(w1.y, hb[bi], acc[12 + bi]);
                    }
                }
            } else {       // light: h1 chunk feeds L1 only
                const int k0 = 512 + (q + 4 * (i - 4)) * 32;
                const float* w1p = s_w1 + k0 * 16 + cp * 4;
#pragma unroll 4
                for (int k = 0; k < 32; k++) {
                    const float4 h4 = *(const float4*)&sh[k * 128 + b0];
                    const ull hb[4] = {bcast2(h4.x), bcast2(h4.y), bcast2(h4.z), bcast2(h4.w)};
                    const ulonglong2 w1 = *(const ulonglong2*)(w1p + k * 16);
#pragma unroll
                    for (int bi = 0; bi < 4; bi++) {
                        acc[8 + bi]  = fma2(w1.x, hb[bi], acc[8 + bi]);
                        acc[12 + bi] = fma2(w1.y, hb[bi], acc[12 + bi]);
                    }
                }
            }
            // poll flag for the chunk filled NEXT iteration (ni2 = i+2)
            if (tl == 0 && i < 6) {
                const int ni2 = i + 2;
                if (ni2 < 4) poll_flag(&g_flagH0[(q + 4 * ni2) * 32], tgtH0);
                else         poll_flag(&g_flagH1[(q + 4 * (ni2 - 4)) * 32], tgtH1);
            }
            asm volatile("bar.sync %0, 128;" :: "r"(1 + q) : "memory");
        }

        // ---- xproj prefetch for L0-gate threads (overlaps dump+reduce) ----
        const int tn = (t + 1 < TT) ? (t + 1) : t;
        float xp[2][4];
        if (tid >= 256) {
            const size_t tb = (size_t)tn * GG;
#pragma unroll
            for (int g = 0; g < 4; g++) {
                xp[0][g] = __ldcg(&g_xproj[(tb + g * 512 + c * 4 + hc0) * BB + bq]);
                xp[1][g] = __ldcg(&g_xproj[(tb + g * 512 + c * 4 + hc0 + 2) * BB + bq]);
            }
        }

        // ---- all quarters dump partials to their even slot ----
        {
            ull* pb = (ull*)(s_stage + (2 * q) * 4096);
#pragma unroll
            for (int i = 0; i < 16; i++) pb[i * 128 + tl] = acc[i];
        }
        __syncthreads();

        // ---- parallel reduce: each thread 4 positions (stride 512) ----
        {
            const ull* P0 = (const ull*)(s_stage + 0 * 4096);
            const ull* P1 = (const ull*)(s_stage + 2 * 4096);
            const ull* P2 = (const ull*)(s_stage + 4 * 4096);
            const ull* P3 = (const ull*)(s_stage + 6 * 4096);
#pragma unroll
            for (int j = 0; j < 4; j++) {
                const int pos = tid + j * 512;
                const ull v = add2(add2(P0[pos], P1[pos]), add2(P2[pos], P3[pos]));
                const int i = pos >> 7, t2 = pos & 127;
                const int ly = i >> 3, pp = (i >> 2) & 1, bi = i & 3;
                const int l = 4 * (t2 & 3) + 2 * pp;
                const int b = 4 * (t2 >> 2) + bi;
                float* dst = ly ? gL1buf : gL0buf;
                const float2 f = unpk2(v);
                dst[l * 132 + b]       = f.x;
                dst[(l + 1) * 132 + b] = f.y;
            }
        }
        __syncthreads();

        // ---- gates: tid<256 -> L1(t); tid>=256 -> L0(t+1) ----
        if (tid < 256) {
#pragma unroll
            for (int r = 0; r < 2; r++) {
                int hc = hc0 + 2 * r;
                int gc = c * 4 + hc;
                float gi = gL1buf[(0 * 4 + hc) * 132 + bq] + b1r[r][0];
                float gj = gL1buf[(1 * 4 + hc) * 132 + bq] + b1r[r][1];
                float gf = gL1buf[(2 * 4 + hc) * 132 + bq] + b1r[r][2];
                float go = gL1buf[(3 * 4 + hc) * 132 + bq] + b1r[r][3];
                float cn = c1s[r] * sigf(gf + 1.0f) + sigf(gi) * tanhf_fast(gj);
                c1s[r] = cn;
                __stcg(&g_h1t[(t & 1) * HB + gc * 128 + bq], tanhf_fast(cn) * sigf(go));
            }
        } else if (t + 1 < TT) {
#pragma unroll
            for (int r = 0; r < 2; r++) {
                int hc = hc0 + 2 * r;
                int gc = c * 4 + hc;
                float gi = gL0buf[(0 * 4 + hc) * 132 + bq] + xp[r][0];
                float gj = gL0buf[(1 * 4 + hc) * 132 + bq] + xp[r][1];
                float gf = gL0buf[(2 * 4 + hc) * 132 + bq] + xp[r][2];
                float go = gL0buf[(3 * 4 + hc) * 132 + bq] + xp[r][3];
                float cn = c0s[r] * sigf(gf + 1.0f) + sigf(gi) * tanhf_fast(gj);
                c0s[r] = cn;
                __stcg(&g_h0t[((t + 1) & 1) * HB + gc * 128 + bq], tanhf_fast(cn) * sigf(go));
            }
        }
        __syncthreads();   // all gate-buffer reads done before next-step fills
        if (tid == 0) arrive_flag(&g_flagH1[mychunk * 32]);
        if (tid == 256 && t + 1 < TT) arrive_flag(&g_flagH0[mychunk * 32]);
    }

    // ---- final projection: logits = h1(T-1) . Wd + bd ----
    if (blockIdx.x == 0) {
        if (tid < 16) poll_flag(&g_flagH1[tid * 32], 8u * TT);
        __syncthreads();
        if (tid < 256) {
            const int b = tid & 127, oc = tid >> 7;
            const float* hf = g_h1t + ((TT - 1) & 1) * HB;
            float s = 0.0f;
#pragma unroll 8
            for (int k = 0; k < HH; k++)
                s += __ldcg(&hf[k * 128 + b]) * Wd[k * 2 + oc];
            out[b * 2 + oc] = s + bd[oc];
        }
    }
}

// ---------------- launch ----------------
extern "C" void kernel_launch(void* const* d_in, const int* in_sizes, int n_in,
                              void* d_out, int out_size) {
    const int* xw    = (const int*)d_in[0];
    const float* emb = (const float*)d_in[1];
    const float* W0  = (const float*)d_in[2];
    const float* b0  = (const float*)d_in[3];
    const float* W1  = (const float*)d_in[4];
    const float* b1  = (const float*)d_in[5];
    const float* Wd  = (const float*)d_in[6];
    const float* bd  = (const float*)d_in[7];
    float* out       = (float*)d_out;
    (void)n_in; (void)out_size;

    const int nx   = in_sizes[0];
    const int vmax = in_sizes[1] / EE - 1;

    // weights 24576 f + staging 32768 f = 57344 f = 229376 B (<= cap)
    const int smemBytes = (24576 + 32768) * sizeof(float);
    cudaFuncSetAttribute(lstm_kernel, cudaFuncAttributeMaxDynamicSharedMemorySize, smemBytes);

    pack_kernel<<<8192, 256>>>(W0, W1);
    detect_kernel<<<(nx / 2 + 255) / 256, 256>>>(xw, nx);
    xproj_kernel<<<dim3(16, TT), 256>>>(xw, emb, W0, b0, vmax);
    lstm_kernel<<<BB, 512, smemBytes>>>(b1, Wd, bd, out);
}